// round 1
// baseline (speedup 1.0000x reference)
#include <cuda_runtime.h>
#include <math.h>

// ---------------------------------------------------------------------------
// MMD-VAE forward, fp32 baseline.
// Shapes: B=8, S=512 -> N=4096 rows; D=1024, DI=4096, DL=64.
//   latent = LN64( gelu(hidden @ enc_w1 + b1) @ enc_w2 + b2 )
//   recon  = LN1024( gelu(latent @ dec_w1 + b1) @ dec_w2 + b2 )
//   loss   = ( K(t,t) + K(l,l) - 2 K(t,l) ) * 64     (RBF mean, d=64)
// Output packing: [recon (4096*1024) | latent (4096*64) | loss (1)]
// ---------------------------------------------------------------------------

#define NR 4096
#define DD 1024
#define DI 4096
#define DL 64

// scratch: one 4096x4096 fp32 buffer reused by both FFN hidden activations
__device__ float g_h[(size_t)4096 * 4096];
__device__ float g_x2[4096];
__device__ float g_y2[4096];
__device__ double g_acc[3];

__device__ __forceinline__ float gelu_f(float x) {
    return 0.5f * x * (1.0f + erff(x * 0.70710678118654752440f));
}

// ---------------------------------------------------------------------------
// Generic GEMM: C[M,N] = A[M,K] @ B[K,N] + bias[N], optional exact GELU.
// 128x128 tile, BK=16, 256 threads, 8x8 per thread. All dims multiples of tile.
// ---------------------------------------------------------------------------
template <bool GELU>
__global__ __launch_bounds__(256) void gemm_bias(
    const float* __restrict__ A, const float* __restrict__ B,
    const float* __restrict__ bias, float* __restrict__ C,
    int M, int N, int K)
{
    __shared__ float As[16][128];
    __shared__ float Bs[16][128];
    const int tid = threadIdx.x;
    const int bm = blockIdx.y * 128;
    const int bn = blockIdx.x * 128;
    const int ty = tid >> 4, tx = tid & 15;

    float acc[8][8];
#pragma unroll
    for (int i = 0; i < 8; i++)
#pragma unroll
        for (int j = 0; j < 8; j++) acc[i][j] = 0.0f;

    for (int k0 = 0; k0 < K; k0 += 16) {
        // A tile 128x16 -> transposed into As[k][row]
#pragma unroll
        for (int i = 0; i < 2; i++) {
            int id = tid * 2 + i;               // 0..511 float4s
            int r = id >> 2, c = (id & 3) << 2; // row 0..127, col 0..12
            const float4 v = *(const float4*)(A + (size_t)(bm + r) * K + k0 + c);
            As[c + 0][r] = v.x; As[c + 1][r] = v.y;
            As[c + 2][r] = v.z; As[c + 3][r] = v.w;
        }
        // B tile 16x128, row-major
#pragma unroll
        for (int i = 0; i < 2; i++) {
            int id = tid * 2 + i;
            int r = id >> 5, c = (id & 31) << 2;
            *(float4*)&Bs[r][c] = *(const float4*)(B + (size_t)(k0 + r) * N + bn + c);
        }
        __syncthreads();
#pragma unroll
        for (int k = 0; k < 16; k++) {
            float4 a0 = *(const float4*)&As[k][ty * 8];
            float4 a1 = *(const float4*)&As[k][ty * 8 + 4];
            float4 b0 = *(const float4*)&Bs[k][tx * 8];
            float4 b1 = *(const float4*)&Bs[k][tx * 8 + 4];
            float a[8] = {a0.x, a0.y, a0.z, a0.w, a1.x, a1.y, a1.z, a1.w};
            float b[8] = {b0.x, b0.y, b0.z, b0.w, b1.x, b1.y, b1.z, b1.w};
#pragma unroll
            for (int i = 0; i < 8; i++)
#pragma unroll
                for (int j = 0; j < 8; j++)
                    acc[i][j] = fmaf(a[i], b[j], acc[i][j]);
        }
        __syncthreads();
    }

#pragma unroll
    for (int i = 0; i < 8; i++) {
        size_t row = (size_t)(bm + ty * 8 + i);
#pragma unroll
        for (int j = 0; j < 8; j += 4) {
            int col = bn + tx * 8 + j;
            float4 v;
            v.x = acc[i][j + 0] + bias[col + 0];
            v.y = acc[i][j + 1] + bias[col + 1];
            v.z = acc[i][j + 2] + bias[col + 2];
            v.w = acc[i][j + 3] + bias[col + 3];
            if (GELU) {
                v.x = gelu_f(v.x); v.y = gelu_f(v.y);
                v.z = gelu_f(v.z); v.w = gelu_f(v.w);
            }
            *(float4*)(C + row * N + col) = v;
        }
    }
}

// ---------------------------------------------------------------------------
// GEMM2 fused with LayerNorm over DL=64:
//   out[4096,64] = LN64( A[4096,4096] @ B[4096,64] + bias )
// Block handles 64 full rows (all 64 cols) so LN is in-block.
// ---------------------------------------------------------------------------
__global__ __launch_bounds__(256) void gemm2_ln(
    const float* __restrict__ A, const float* __restrict__ B,
    const float* __restrict__ bias, const float* __restrict__ lg,
    const float* __restrict__ lb, float* __restrict__ out)
{
    __shared__ float As[16][64];
    __shared__ float Bs[16][64];
    __shared__ float Cs[64][65];
    const int tid = threadIdx.x;
    const int bm = blockIdx.x * 64;
    const int ty = tid >> 4, tx = tid & 15;

    float acc[4][4];
#pragma unroll
    for (int i = 0; i < 4; i++)
#pragma unroll
        for (int j = 0; j < 4; j++) acc[i][j] = 0.0f;

    for (int k0 = 0; k0 < DI; k0 += 16) {
        {   // A tile 64x16 -> transposed
            int r = tid >> 2, c = (tid & 3) << 2;
            const float4 v = *(const float4*)(A + (size_t)(bm + r) * DI + k0 + c);
            As[c + 0][r] = v.x; As[c + 1][r] = v.y;
            As[c + 2][r] = v.z; As[c + 3][r] = v.w;
        }
        {   // B tile 16x64
            int r = tid >> 4, c = (tid & 15) << 2;
            *(float4*)&Bs[r][c] = *(const float4*)(B + (size_t)(k0 + r) * DL + c);
        }
        __syncthreads();
#pragma unroll
        for (int k = 0; k < 16; k++) {
            float4 a = *(const float4*)&As[k][ty * 4];
            float4 b = *(const float4*)&Bs[k][tx * 4];
            float av[4] = {a.x, a.y, a.z, a.w};
            float bv[4] = {b.x, b.y, b.z, b.w};
#pragma unroll
            for (int i = 0; i < 4; i++)
#pragma unroll
                for (int j = 0; j < 4; j++)
                    acc[i][j] = fmaf(av[i], bv[j], acc[i][j]);
        }
        __syncthreads();
    }

#pragma unroll
    for (int i = 0; i < 4; i++)
#pragma unroll
        for (int j = 0; j < 4; j++)
            Cs[ty * 4 + i][tx * 4 + j] = acc[i][j] + bias[tx * 4 + j];
    __syncthreads();

    if (tid < 64) {
        float mu = 0.0f;
#pragma unroll
        for (int j = 0; j < 64; j++) mu += Cs[tid][j];
        mu *= (1.0f / 64.0f);
        float var = 0.0f;
#pragma unroll
        for (int j = 0; j < 64; j++) {
            float d = Cs[tid][j] - mu;
            var = fmaf(d, d, var);
        }
        var *= (1.0f / 64.0f);
        float rs = rsqrtf(var + 1e-9f);
        float* op = out + (size_t)(bm + tid) * DL;
#pragma unroll
        for (int j = 0; j < 64; j++)
            op[j] = (Cs[tid][j] - mu) * rs * lg[j] + lb[j];
    }
}

// ---------------------------------------------------------------------------
// In-place LayerNorm over D=1024, one block per row, 256 threads.
// ---------------------------------------------------------------------------
__device__ __forceinline__ float block_sum_256(float v, float* red) {
#pragma unroll
    for (int o = 16; o; o >>= 1) v += __shfl_xor_sync(0xffffffffu, v, o);
    if ((threadIdx.x & 31) == 0) red[threadIdx.x >> 5] = v;
    __syncthreads();
    float t = 0.0f;
#pragma unroll
    for (int i = 0; i < 8; i++) t += red[i];
    __syncthreads();
    return t;
}

__global__ __launch_bounds__(256) void ln1024(
    float* __restrict__ x, const float* __restrict__ lg, const float* __restrict__ lb)
{
    __shared__ float red[8];
    float* p = x + (size_t)blockIdx.x * DD;
    const int tid = threadIdx.x;
    float v[4];
    float s = 0.0f;
#pragma unroll
    for (int i = 0; i < 4; i++) { v[i] = p[tid + i * 256]; s += v[i]; }
    float mu = block_sum_256(s, red) * (1.0f / 1024.0f);
    float s2 = 0.0f;
#pragma unroll
    for (int i = 0; i < 4; i++) {
        float d = v[i] - mu;
        s2 = fmaf(d, d, s2);
    }
    float var = block_sum_256(s2, red) * (1.0f / 1024.0f);
    float rs = rsqrtf(var + 1e-9f);
#pragma unroll
    for (int i = 0; i < 4; i++) {
        int col = tid + i * 256;
        p[col] = (v[i] - mu) * rs * lg[col] + lb[col];
    }
}

// ---------------------------------------------------------------------------
// Per-row squared norms for DL=64 vectors. One warp per row.
// ---------------------------------------------------------------------------
__global__ __launch_bounds__(256) void rowsq(
    const float* __restrict__ X, float* __restrict__ o)
{
    int row = blockIdx.x * 8 + (threadIdx.x >> 5);
    int lane = threadIdx.x & 31;
    const float* p = X + (size_t)row * DL;
    float a = p[lane], b = p[lane + 32];
    float s = fmaf(a, a, b * b);
#pragma unroll
    for (int off = 16; off; off >>= 1) s += __shfl_xor_sync(0xffffffffu, s, off);
    if (lane == 0) o[row] = s;
}

// ---------------------------------------------------------------------------
// RBF kernel-mean tile: sum over exp(-(|x|^2+|y|^2-2 x.y)/4096) for a 64x64
// tile of the 4096x4096 kernel matrix, accumulated into a double.
// ---------------------------------------------------------------------------
__global__ __launch_bounds__(256) void mmd_tile(
    const float* __restrict__ X, const float* __restrict__ Y,
    const float* __restrict__ x2, const float* __restrict__ y2,
    double* __restrict__ acc)
{
    __shared__ float Xs[64][64];   // [k][row]
    __shared__ float Ys[64][64];   // [k][row]
    const int tid = threadIdx.x;
    const int bi = blockIdx.y * 64, bj = blockIdx.x * 64;

#pragma unroll
    for (int i = 0; i < 4; i++) {
        int id = tid + 256 * i;             // float4 index 0..1023
        int r = id >> 4, c = (id & 15) << 2;
        float4 vx = *(const float4*)(X + (size_t)(bi + r) * DL + c);
        Xs[c + 0][r] = vx.x; Xs[c + 1][r] = vx.y;
        Xs[c + 2][r] = vx.z; Xs[c + 3][r] = vx.w;
        float4 vy = *(const float4*)(Y + (size_t)(bj + r) * DL + c);
        Ys[c + 0][r] = vy.x; Ys[c + 1][r] = vy.y;
        Ys[c + 2][r] = vy.z; Ys[c + 3][r] = vy.w;
    }
    __syncthreads();

    const int ty = tid >> 4, tx = tid & 15;
    float s[4][4];
#pragma unroll
    for (int i = 0; i < 4; i++)
#pragma unroll
        for (int j = 0; j < 4; j++) s[i][j] = 0.0f;

#pragma unroll
    for (int k = 0; k < 64; k++) {
        float4 a = *(const float4*)&Xs[k][ty * 4];
        float4 b = *(const float4*)&Ys[k][tx * 4];
        float av[4] = {a.x, a.y, a.z, a.w};
        float bv[4] = {b.x, b.y, b.z, b.w};
#pragma unroll
        for (int i = 0; i < 4; i++)
#pragma unroll
            for (int j = 0; j < 4; j++)
                s[i][j] = fmaf(av[i], bv[j], s[i][j]);
    }

    float xi[4], yj[4];
#pragma unroll
    for (int i = 0; i < 4; i++) xi[i] = x2[bi + ty * 4 + i];
#pragma unroll
    for (int j = 0; j < 4; j++) yj[j] = y2[bj + tx * 4 + j];

    float lsum = 0.0f;
#pragma unroll
    for (int i = 0; i < 4; i++)
#pragma unroll
        for (int j = 0; j < 4; j++) {
            float sq = xi[i] + yj[j] - 2.0f * s[i][j];
            lsum += __expf(sq * (-1.0f / 4096.0f));
        }

#pragma unroll
    for (int off = 16; off; off >>= 1)
        lsum += __shfl_xor_sync(0xffffffffu, lsum, off);

    __shared__ float ws[8];
    if ((tid & 31) == 0) ws[tid >> 5] = lsum;
    __syncthreads();
    if (tid == 0) {
        double t = 0.0;
#pragma unroll
        for (int w = 0; w < 8; w++) t += (double)ws[w];
        atomicAdd(acc, t);
    }
}

__global__ void zero_acc_k() {
    if (threadIdx.x < 3) g_acc[threadIdx.x] = 0.0;
}

__global__ void finalize_loss(float* __restrict__ out) {
    const double inv = 1.0 / (4096.0 * 4096.0);
    double mmd = (g_acc[0] + g_acc[1] - 2.0 * g_acc[2]) * inv;
    out[0] = (float)(mmd * 64.0);   // mmd / B * S = mmd / 8 * 512
}

// ---------------------------------------------------------------------------
extern "C" void kernel_launch(void* const* d_in, const int* in_sizes, int n_in,
                              void* d_out, int out_size)
{
    const float* hidden = (const float*)d_in[0];
    const float* true_s = (const float*)d_in[1];
    const float* enc_w1 = (const float*)d_in[2];
    const float* enc_b1 = (const float*)d_in[3];
    const float* enc_w2 = (const float*)d_in[4];
    const float* enc_b2 = (const float*)d_in[5];
    const float* enc_g  = (const float*)d_in[6];
    const float* enc_lb = (const float*)d_in[7];
    const float* dec_w1 = (const float*)d_in[8];
    const float* dec_b1 = (const float*)d_in[9];
    const float* dec_w2 = (const float*)d_in[10];
    const float* dec_b2 = (const float*)d_in[11];
    const float* dec_g  = (const float*)d_in[12];
    const float* dec_lb = (const float*)d_in[13];

    float* recon  = (float*)d_out;                       // 4096*1024
    float* latent = recon + (size_t)NR * DD;             // 4096*64
    float* loss   = latent + (size_t)NR * DL;            // 1

    float*  h;    cudaGetSymbolAddress((void**)&h,   g_h);
    float*  x2;   cudaGetSymbolAddress((void**)&x2,  g_x2);
    float*  y2;   cudaGetSymbolAddress((void**)&y2,  g_y2);
    double* acc;  cudaGetSymbolAddress((void**)&acc, g_acc);

    zero_acc_k<<<1, 32>>>();

    // encoder
    gemm_bias<true><<<dim3(DI / 128, NR / 128), 256>>>(hidden, enc_w1, enc_b1, h,
                                                       NR, DI, DD);
    gemm2_ln<<<NR / 64, 256>>>(h, enc_w2, enc_b2, enc_g, enc_lb, latent);

    // decoder
    gemm_bias<true><<<dim3(DI / 128, NR / 128), 256>>>(latent, dec_w1, dec_b1, h,
                                                       NR, DI, DL);
    gemm_bias<false><<<dim3(DD / 128, NR / 128), 256>>>(h, dec_w2, dec_b2, recon,
                                                        NR, DD, DI);
    ln1024<<<NR, 256>>>(recon, dec_g, dec_lb);

    // MMD
    rowsq<<<NR / 8, 256>>>(true_s, x2);
    rowsq<<<NR / 8, 256>>>(latent, y2);
    mmd_tile<<<dim3(64, 64), 256>>>(true_s, true_s, x2, x2, acc + 0);
    mmd_tile<<<dim3(64, 64), 256>>>(latent, latent, y2, y2, acc + 1);
    mmd_tile<<<dim3(64, 64), 256>>>(true_s, latent, x2, y2, acc + 2);
    finalize_loss<<<1, 1>>>(loss);
}

// round 2
// speedup vs baseline: 1.0007x; 1.0007x over previous
#include <cuda_runtime.h>
#include <math.h>

// ---------------------------------------------------------------------------
// MMD-VAE forward, fp32 baseline.
// Shapes: B=8, S=512 -> N=4096 rows; D=1024, DI=4096, DL=64.
//   latent = LN64( gelu(hidden @ enc_w1 + b1) @ enc_w2 + b2 )
//   recon  = LN1024( gelu(latent @ dec_w1 + b1) @ dec_w2 + b2 )
//   loss   = ( K(t,t) + K(l,l) - 2 K(t,l) ) * 64     (RBF mean, d=64)
// Output packing: [recon (4096*1024) | latent (4096*64) | loss (1)]
// ---------------------------------------------------------------------------

#define NR 4096
#define DD 1024
#define DI 4096
#define DL 64

// scratch: one 4096x4096 fp32 buffer reused by both FFN hidden activations
__device__ float g_h[(size_t)4096 * 4096];
__device__ float g_x2[4096];
__device__ float g_y2[4096];
__device__ double g_acc[3];

__device__ __forceinline__ float gelu_f(float x) {
    return 0.5f * x * (1.0f + erff(x * 0.70710678118654752440f));
}

// ---------------------------------------------------------------------------
// Generic GEMM: C[M,N] = A[M,K] @ B[K,N] + bias[N], optional exact GELU.
// 128x128 tile, BK=16, 256 threads, 8x8 per thread. All dims multiples of tile.
// ---------------------------------------------------------------------------
template <bool GELU>
__global__ __launch_bounds__(256) void gemm_bias(
    const float* __restrict__ A, const float* __restrict__ B,
    const float* __restrict__ bias, float* __restrict__ C,
    int M, int N, int K)
{
    __shared__ float As[16][128];
    __shared__ float Bs[16][128];
    const int tid = threadIdx.x;
    const int bm = blockIdx.y * 128;
    const int bn = blockIdx.x * 128;
    const int ty = tid >> 4, tx = tid & 15;

    float acc[8][8];
#pragma unroll
    for (int i = 0; i < 8; i++)
#pragma unroll
        for (int j = 0; j < 8; j++) acc[i][j] = 0.0f;

    for (int k0 = 0; k0 < K; k0 += 16) {
        // A tile 128x16 -> transposed into As[k][row]
#pragma unroll
        for (int i = 0; i < 2; i++) {
            int id = tid * 2 + i;               // 0..511 float4s
            int r = id >> 2, c = (id & 3) << 2; // row 0..127, col 0..12
            const float4 v = *(const float4*)(A + (size_t)(bm + r) * K + k0 + c);
            As[c + 0][r] = v.x; As[c + 1][r] = v.y;
            As[c + 2][r] = v.z; As[c + 3][r] = v.w;
        }
        // B tile 16x128, row-major
#pragma unroll
        for (int i = 0; i < 2; i++) {
            int id = tid * 2 + i;
            int r = id >> 5, c = (id & 31) << 2;
            *(float4*)&Bs[r][c] = *(const float4*)(B + (size_t)(k0 + r) * N + bn + c);
        }
        __syncthreads();
#pragma unroll
        for (int k = 0; k < 16; k++) {
            float4 a0 = *(const float4*)&As[k][ty * 8];
            float4 a1 = *(const float4*)&As[k][ty * 8 + 4];
            float4 b0 = *(const float4*)&Bs[k][tx * 8];
            float4 b1 = *(const float4*)&Bs[k][tx * 8 + 4];
            float a[8] = {a0.x, a0.y, a0.z, a0.w, a1.x, a1.y, a1.z, a1.w};
            float b[8] = {b0.x, b0.y, b0.z, b0.w, b1.x, b1.y, b1.z, b1.w};
#pragma unroll
            for (int i = 0; i < 8; i++)
#pragma unroll
                for (int j = 0; j < 8; j++)
                    acc[i][j] = fmaf(a[i], b[j], acc[i][j]);
        }
        __syncthreads();
    }

#pragma unroll
    for (int i = 0; i < 8; i++) {
        size_t row = (size_t)(bm + ty * 8 + i);
#pragma unroll
        for (int j = 0; j < 8; j += 4) {
            int col = bn + tx * 8 + j;
            float4 v;
            v.x = acc[i][j + 0] + bias[col + 0];
            v.y = acc[i][j + 1] + bias[col + 1];
            v.z = acc[i][j + 2] + bias[col + 2];
            v.w = acc[i][j + 3] + bias[col + 3];
            if (GELU) {
                v.x = gelu_f(v.x); v.y = gelu_f(v.y);
                v.z = gelu_f(v.z); v.w = gelu_f(v.w);
            }
            *(float4*)(C + row * N + col) = v;
        }
    }
}

// ---------------------------------------------------------------------------
// GEMM2 fused with LayerNorm over DL=64:
//   out[4096,64] = LN64( A[4096,4096] @ B[4096,64] + bias )
// Block handles 64 full rows (all 64 cols) so LN is in-block.
// ---------------------------------------------------------------------------
__global__ __launch_bounds__(256) void gemm2_ln(
    const float* __restrict__ A, const float* __restrict__ B,
    const float* __restrict__ bias, const float* __restrict__ lg,
    const float* __restrict__ lb, float* __restrict__ out)
{
    __shared__ float As[16][64];
    __shared__ float Bs[16][64];
    __shared__ float Cs[64][65];
    const int tid = threadIdx.x;
    const int bm = blockIdx.x * 64;
    const int ty = tid >> 4, tx = tid & 15;

    float acc[4][4];
#pragma unroll
    for (int i = 0; i < 4; i++)
#pragma unroll
        for (int j = 0; j < 4; j++) acc[i][j] = 0.0f;

    for (int k0 = 0; k0 < DI; k0 += 16) {
        {   // A tile 64x16 -> transposed
            int r = tid >> 2, c = (tid & 3) << 2;
            const float4 v = *(const float4*)(A + (size_t)(bm + r) * DI + k0 + c);
            As[c + 0][r] = v.x; As[c + 1][r] = v.y;
            As[c + 2][r] = v.z; As[c + 3][r] = v.w;
        }
        {   // B tile 16x64
            int r = tid >> 4, c = (tid & 15) << 2;
            *(float4*)&Bs[r][c] = *(const float4*)(B + (size_t)(k0 + r) * DL + c);
        }
        __syncthreads();
#pragma unroll
        for (int k = 0; k < 16; k++) {
            float4 a = *(const float4*)&As[k][ty * 4];
            float4 b = *(const float4*)&Bs[k][tx * 4];
            float av[4] = {a.x, a.y, a.z, a.w};
            float bv[4] = {b.x, b.y, b.z, b.w};
#pragma unroll
            for (int i = 0; i < 4; i++)
#pragma unroll
                for (int j = 0; j < 4; j++)
                    acc[i][j] = fmaf(av[i], bv[j], acc[i][j]);
        }
        __syncthreads();
    }

#pragma unroll
    for (int i = 0; i < 4; i++)
#pragma unroll
        for (int j = 0; j < 4; j++)
            Cs[ty * 4 + i][tx * 4 + j] = acc[i][j] + bias[tx * 4 + j];
    __syncthreads();

    if (tid < 64) {
        float mu = 0.0f;
#pragma unroll
        for (int j = 0; j < 64; j++) mu += Cs[tid][j];
        mu *= (1.0f / 64.0f);
        float var = 0.0f;
#pragma unroll
        for (int j = 0; j < 64; j++) {
            float d = Cs[tid][j] - mu;
            var = fmaf(d, d, var);
        }
        var *= (1.0f / 64.0f);
        float rs = rsqrtf(var + 1e-9f);
        float* op = out + (size_t)(bm + tid) * DL;
#pragma unroll
        for (int j = 0; j < 64; j++)
            op[j] = (Cs[tid][j] - mu) * rs * lg[j] + lb[j];
    }
}

// ---------------------------------------------------------------------------
// In-place LayerNorm over D=1024, one block per row, 256 threads.
// ---------------------------------------------------------------------------
__device__ __forceinline__ float block_sum_256(float v, float* red) {
#pragma unroll
    for (int o = 16; o; o >>= 1) v += __shfl_xor_sync(0xffffffffu, v, o);
    if ((threadIdx.x & 31) == 0) red[threadIdx.x >> 5] = v;
    __syncthreads();
    float t = 0.0f;
#pragma unroll
    for (int i = 0; i < 8; i++) t += red[i];
    __syncthreads();
    return t;
}

__global__ __launch_bounds__(256) void ln1024(
    float* __restrict__ x, const float* __restrict__ lg, const float* __restrict__ lb)
{
    __shared__ float red[8];
    float* p = x + (size_t)blockIdx.x * DD;
    const int tid = threadIdx.x;
    float v[4];
    float s = 0.0f;
#pragma unroll
    for (int i = 0; i < 4; i++) { v[i] = p[tid + i * 256]; s += v[i]; }
    float mu = block_sum_256(s, red) * (1.0f / 1024.0f);
    float s2 = 0.0f;
#pragma unroll
    for (int i = 0; i < 4; i++) {
        float d = v[i] - mu;
        s2 = fmaf(d, d, s2);
    }
    float var = block_sum_256(s2, red) * (1.0f / 1024.0f);
    float rs = rsqrtf(var + 1e-9f);
#pragma unroll
    for (int i = 0; i < 4; i++) {
        int col = tid + i * 256;
        p[col] = (v[i] - mu) * rs * lg[col] + lb[col];
    }
}

// ---------------------------------------------------------------------------
// Per-row squared norms for DL=64 vectors. One warp per row.
// ---------------------------------------------------------------------------
__global__ __launch_bounds__(256) void rowsq(
    const float* __restrict__ X, float* __restrict__ o)
{
    int row = blockIdx.x * 8 + (threadIdx.x >> 5);
    int lane = threadIdx.x & 31;
    const float* p = X + (size_t)row * DL;
    float a = p[lane], b = p[lane + 32];
    float s = fmaf(a, a, b * b);
#pragma unroll
    for (int off = 16; off; off >>= 1) s += __shfl_xor_sync(0xffffffffu, s, off);
    if (lane == 0) o[row] = s;
}

// ---------------------------------------------------------------------------
// RBF kernel-mean tile: sum over exp(-(|x|^2+|y|^2-2 x.y)/4096) for a 64x64
// tile of the 4096x4096 kernel matrix, accumulated into a double.
// ---------------------------------------------------------------------------
__global__ __launch_bounds__(256) void mmd_tile(
    const float* __restrict__ X, const float* __restrict__ Y,
    const float* __restrict__ x2, const float* __restrict__ y2,
    double* __restrict__ acc)
{
    __shared__ float Xs[64][64];   // [k][row]
    __shared__ float Ys[64][64];   // [k][row]
    const int tid = threadIdx.x;
    const int bi = blockIdx.y * 64, bj = blockIdx.x * 64;

#pragma unroll
    for (int i = 0; i < 4; i++) {
        int id = tid + 256 * i;             // float4 index 0..1023
        int r = id >> 4, c = (id & 15) << 2;
        float4 vx = *(const float4*)(X + (size_t)(bi + r) * DL + c);
        Xs[c + 0][r] = vx.x; Xs[c + 1][r] = vx.y;
        Xs[c + 2][r] = vx.z; Xs[c + 3][r] = vx.w;
        float4 vy = *(const float4*)(Y + (size_t)(bj + r) * DL + c);
        Ys[c + 0][r] = vy.x; Ys[c + 1][r] = vy.y;
        Ys[c + 2][r] = vy.z; Ys[c + 3][r] = vy.w;
    }
    __syncthreads();

    const int ty = tid >> 4, tx = tid & 15;
    float s[4][4];
#pragma unroll
    for (int i = 0; i < 4; i++)
#pragma unroll
        for (int j = 0; j < 4; j++) s[i][j] = 0.0f;

#pragma unroll
    for (int k = 0; k < 64; k++) {
        float4 a = *(const float4*)&Xs[k][ty * 4];
        float4 b = *(const float4*)&Ys[k][tx * 4];
        float av[4] = {a.x, a.y, a.z, a.w};
        float bv[4] = {b.x, b.y, b.z, b.w};
#pragma unroll
        for (int i = 0; i < 4; i++)
#pragma unroll
            for (int j = 0; j < 4; j++)
                s[i][j] = fmaf(av[i], bv[j], s[i][j]);
    }

    float xi[4], yj[4];
#pragma unroll
    for (int i = 0; i < 4; i++) xi[i] = x2[bi + ty * 4 + i];
#pragma unroll
    for (int j = 0; j < 4; j++) yj[j] = y2[bj + tx * 4 + j];

    float lsum = 0.0f;
#pragma unroll
    for (int i = 0; i < 4; i++)
#pragma unroll
        for (int j = 0; j < 4; j++) {
            float sq = xi[i] + yj[j] - 2.0f * s[i][j];
            lsum += __expf(sq * (-1.0f / 4096.0f));
        }

#pragma unroll
    for (int off = 16; off; off >>= 1)
        lsum += __shfl_xor_sync(0xffffffffu, lsum, off);

    __shared__ float ws[8];
    if ((tid & 31) == 0) ws[tid >> 5] = lsum;
    __syncthreads();
    if (tid == 0) {
        double t = 0.0;
#pragma unroll
        for (int w = 0; w < 8; w++) t += (double)ws[w];
        atomicAdd(acc, t);
    }
}

__global__ void zero_acc_k() {
    if (threadIdx.x < 3) g_acc[threadIdx.x] = 0.0;
}

__global__ void finalize_loss(float* __restrict__ out) {
    const double inv = 1.0 / (4096.0 * 4096.0);
    double mmd = (g_acc[0] + g_acc[1] - 2.0 * g_acc[2]) * inv;
    out[0] = (float)(mmd * 64.0);   // mmd / B * S = mmd / 8 * 512
}

// ---------------------------------------------------------------------------
extern "C" void kernel_launch(void* const* d_in, const int* in_sizes, int n_in,
                              void* d_out, int out_size)
{
    const float* hidden = (const float*)d_in[0];
    const float* true_s = (const float*)d_in[1];
    const float* enc_w1 = (const float*)d_in[2];
    const float* enc_b1 = (const float*)d_in[3];
    const float* enc_w2 = (const float*)d_in[4];
    const float* enc_b2 = (const float*)d_in[5];
    const float* enc_g  = (const float*)d_in[6];
    const float* enc_lb = (const float*)d_in[7];
    const float* dec_w1 = (const float*)d_in[8];
    const float* dec_b1 = (const float*)d_in[9];
    const float* dec_w2 = (const float*)d_in[10];
    const float* dec_b2 = (const float*)d_in[11];
    const float* dec_g  = (const float*)d_in[12];
    const float* dec_lb = (const float*)d_in[13];

    float* recon  = (float*)d_out;                       // 4096*1024
    float* latent = recon + (size_t)NR * DD;             // 4096*64
    float* loss   = latent + (size_t)NR * DL;            // 1

    float*  h;    cudaGetSymbolAddress((void**)&h,   g_h);
    float*  x2;   cudaGetSymbolAddress((void**)&x2,  g_x2);
    float*  y2;   cudaGetSymbolAddress((void**)&y2,  g_y2);
    double* acc;  cudaGetSymbolAddress((void**)&acc, g_acc);

    zero_acc_k<<<1, 32>>>();

    // encoder
    gemm_bias<true><<<dim3(DI / 128, NR / 128), 256>>>(hidden, enc_w1, enc_b1, h,
                                                       NR, DI, DD);
    gemm2_ln<<<NR / 64, 256>>>(h, enc_w2, enc_b2, enc_g, enc_lb, latent);

    // decoder
    gemm_bias<true><<<dim3(DI / 128, NR / 128), 256>>>(latent, dec_w1, dec_b1, h,
                                                       NR, DI, DL);
    gemm_bias<false><<<dim3(DD / 128, NR / 128), 256>>>(h, dec_w2, dec_b2, recon,
                                                        NR, DD, DI);
    ln1024<<<NR, 256>>>(recon, dec_g, dec_lb);

    // MMD
    rowsq<<<NR / 8, 256>>>(true_s, x2);
    rowsq<<<NR / 8, 256>>>(latent, y2);
    mmd_tile<<<dim3(64, 64), 256>>>(true_s, true_s, x2, x2, acc + 0);
    mmd_tile<<<dim3(64, 64), 256>>>(latent, latent, y2, y2, acc + 1);
    mmd_tile<<<dim3(64, 64), 256>>>(true_s, latent, x2, y2, acc + 2);
    finalize_loss<<<1, 1>>>(loss);
}

// round 3
// speedup vs baseline: 2.6961x; 2.6941x over previous
#include <cuda_runtime.h>
#include <math.h>

#define NR 4096
#define DD 1024
#define DI 4096
#define DL 64
#define KSPLIT 8

// scratch
__device__ float g_h[(size_t)4096 * 4096];          // 64MB hidden activations
__device__ float g_part[(size_t)KSPLIT * 4096 * 64]; // 8MB split-K partials
__device__ float g_x2[4096];
__device__ float g_y2[4096];
__device__ double g_acc[3];

__device__ __forceinline__ float gelu_f(float x) {
    return 0.5f * x * (1.0f + erff(x * 0.70710678118654752440f));
}

__device__ __forceinline__ unsigned f2tf32(float x) {
    unsigned u;
    asm("cvt.rna.tf32.f32 %0, %1;" : "=r"(u) : "f"(x));
    return u;
}

__device__ __forceinline__ void mma_tf32(float* d, const unsigned* a, const unsigned* b) {
    asm volatile(
        "mma.sync.aligned.m16n8k8.row.col.f32.tf32.tf32.f32 "
        "{%0,%1,%2,%3}, {%4,%5,%6,%7}, {%8,%9}, {%0,%1,%2,%3};\n"
        : "+f"(d[0]), "+f"(d[1]), "+f"(d[2]), "+f"(d[3])
        : "r"(a[0]), "r"(a[1]), "r"(a[2]), "r"(a[3]), "r"(b[0]), "r"(b[1]));
}

// ---------------------------------------------------------------------------
// TF32 tensor-core GEMM: C[M,N] = A[M,K] @ B[K,N] + bias, optional GELU.
// BM=128 BN=128 BK=32, 256 threads (8 warps, 2m x 4n), warp tile 64x32.
// M,N multiples of 128; K multiple of 32.
// ---------------------------------------------------------------------------
template <bool GELU>
__global__ __launch_bounds__(256, 2) void gemm_tc(
    const float* __restrict__ A, const float* __restrict__ B,
    const float* __restrict__ bias, float* __restrict__ C,
    int M, int N, int K)
{
    __shared__ float As[128][36];   // [m][k], tf32 bits
    __shared__ float Bs[32][136];   // [k][n], tf32 bits

    const int tid  = threadIdx.x;
    const int warp = tid >> 5, lane = tid & 31;
    const int gid  = lane >> 2, tig = lane & 3;
    const int wm   = (warp & 1) * 64;
    const int wn   = (warp >> 1) * 32;
    const int bm   = blockIdx.y * 128;
    const int bn   = blockIdx.x * 128;

    float d[4][4][4];
#pragma unroll
    for (int i = 0; i < 4; i++)
#pragma unroll
        for (int j = 0; j < 4; j++)
#pragma unroll
            for (int r = 0; r < 4; r++) d[i][j][r] = 0.0f;

    for (int k0 = 0; k0 < K; k0 += 32) {
        // A tile 128x32
#pragma unroll
        for (int it = 0; it < 4; it++) {
            int id = tid + 256 * it;
            int r = id >> 3, c = (id & 7) << 2;
            float4 v = *(const float4*)(A + (size_t)(bm + r) * K + k0 + c);
            float4 w;
            w.x = __uint_as_float(f2tf32(v.x));
            w.y = __uint_as_float(f2tf32(v.y));
            w.z = __uint_as_float(f2tf32(v.z));
            w.w = __uint_as_float(f2tf32(v.w));
            *(float4*)&As[r][c] = w;
        }
        // B tile 32x128
#pragma unroll
        for (int it = 0; it < 4; it++) {
            int id = tid + 256 * it;
            int r = id >> 5, c = (id & 31) << 2;
            float4 v = *(const float4*)(B + (size_t)(k0 + r) * N + bn + c);
            float4 w;
            w.x = __uint_as_float(f2tf32(v.x));
            w.y = __uint_as_float(f2tf32(v.y));
            w.z = __uint_as_float(f2tf32(v.z));
            w.w = __uint_as_float(f2tf32(v.w));
            *(float4*)&Bs[r][c] = w;
        }
        __syncthreads();

#pragma unroll
        for (int ks = 0; ks < 4; ks++) {
            const int k8 = ks * 8;
            unsigned a[4][4], bf[4][2];
#pragma unroll
            for (int i = 0; i < 4; i++) {
                int m = wm + 16 * i + gid;
                a[i][0] = __float_as_uint(As[m][k8 + tig]);
                a[i][1] = __float_as_uint(As[m + 8][k8 + tig]);
                a[i][2] = __float_as_uint(As[m][k8 + tig + 4]);
                a[i][3] = __float_as_uint(As[m + 8][k8 + tig + 4]);
            }
#pragma unroll
            for (int j = 0; j < 4; j++) {
                int n = wn + 8 * j + gid;
                bf[j][0] = __float_as_uint(Bs[k8 + tig][n]);
                bf[j][1] = __float_as_uint(Bs[k8 + tig + 4][n]);
            }
#pragma unroll
            for (int i = 0; i < 4; i++)
#pragma unroll
                for (int j = 0; j < 4; j++)
                    mma_tf32(d[i][j], a[i], bf[j]);
        }
        __syncthreads();
    }

#pragma unroll
    for (int i = 0; i < 4; i++) {
        int row = bm + wm + 16 * i + gid;
#pragma unroll
        for (int j = 0; j < 4; j++) {
            int col = bn + wn + 8 * j + 2 * tig;
            float bx = bias[col], by = bias[col + 1];
            float r0 = d[i][j][0] + bx, r1 = d[i][j][1] + by;
            float r2 = d[i][j][2] + bx, r3 = d[i][j][3] + by;
            if (GELU) {
                r0 = gelu_f(r0); r1 = gelu_f(r1);
                r2 = gelu_f(r2); r3 = gelu_f(r3);
            }
            *(float2*)(C + (size_t)row * N + col)       = make_float2(r0, r1);
            *(float2*)(C + (size_t)(row + 8) * N + col) = make_float2(r2, r3);
        }
    }
}

// ---------------------------------------------------------------------------
// GEMM2 split-K (tf32): part[ks][4096,64] = A[:,ks*512:+512] @ B-slice
// BM=128 BN=64 BK=32, 8 warps (4m x 2n), warp tile 32x32.
// ---------------------------------------------------------------------------
__global__ __launch_bounds__(256, 2) void gemm2_tc(
    const float* __restrict__ A, const float* __restrict__ B,
    float* __restrict__ part)
{
    __shared__ float As[128][36];
    __shared__ float Bs[32][72];

    const int tid  = threadIdx.x;
    const int warp = tid >> 5, lane = tid & 31;
    const int gid  = lane >> 2, tig = lane & 3;
    const int wm   = (warp & 3) * 32;
    const int wn   = (warp >> 2) * 32;
    const int bm   = blockIdx.y * 128;
    const int kbeg = blockIdx.x * (DI / KSPLIT);

    float d[2][4][4];
#pragma unroll
    for (int i = 0; i < 2; i++)
#pragma unroll
        for (int j = 0; j < 4; j++)
#pragma unroll
            for (int r = 0; r < 4; r++) d[i][j][r] = 0.0f;

    for (int kk = 0; kk < DI / KSPLIT; kk += 32) {
        const int k0 = kbeg + kk;
#pragma unroll
        for (int it = 0; it < 4; it++) {
            int id = tid + 256 * it;
            int r = id >> 3, c = (id & 7) << 2;
            float4 v = *(const float4*)(A + (size_t)(bm + r) * DI + k0 + c);
            float4 w;
            w.x = __uint_as_float(f2tf32(v.x));
            w.y = __uint_as_float(f2tf32(v.y));
            w.z = __uint_as_float(f2tf32(v.z));
            w.w = __uint_as_float(f2tf32(v.w));
            *(float4*)&As[r][c] = w;
        }
#pragma unroll
        for (int it = 0; it < 2; it++) {
            int id = tid + 256 * it;
            int r = id >> 4, c = (id & 15) << 2;
            float4 v = *(const float4*)(B + (size_t)(k0 + r) * DL + c);
            float4 w;
            w.x = __uint_as_float(f2tf32(v.x));
            w.y = __uint_as_float(f2tf32(v.y));
            w.z = __uint_as_float(f2tf32(v.z));
            w.w = __uint_as_float(f2tf32(v.w));
            *(float4*)&Bs[r][c] = w;
        }
        __syncthreads();

#pragma unroll
        for (int ks = 0; ks < 4; ks++) {
            const int k8 = ks * 8;
            unsigned a[2][4], bf[4][2];
#pragma unroll
            for (int i = 0; i < 2; i++) {
                int m = wm + 16 * i + gid;
                a[i][0] = __float_as_uint(As[m][k8 + tig]);
                a[i][1] = __float_as_uint(As[m + 8][k8 + tig]);
                a[i][2] = __float_as_uint(As[m][k8 + tig + 4]);
                a[i][3] = __float_as_uint(As[m + 8][k8 + tig + 4]);
            }
#pragma unroll
            for (int j = 0; j < 4; j++) {
                int n = wn + 8 * j + gid;
                bf[j][0] = __float_as_uint(Bs[k8 + tig][n]);
                bf[j][1] = __float_as_uint(Bs[k8 + tig + 4][n]);
            }
#pragma unroll
            for (int i = 0; i < 2; i++)
#pragma unroll
                for (int j = 0; j < 4; j++)
                    mma_tf32(d[i][j], a[i], bf[j]);
        }
        __syncthreads();
    }

    float* op = part + (size_t)blockIdx.x * NR * DL;
#pragma unroll
    for (int i = 0; i < 2; i++) {
        int row = bm + wm + 16 * i + gid;
#pragma unroll
        for (int j = 0; j < 4; j++) {
            int col = wn + 8 * j + 2 * tig;
            *(float2*)(op + (size_t)row * DL + col)       = make_float2(d[i][j][0], d[i][j][1]);
            *(float2*)(op + (size_t)(row + 8) * DL + col) = make_float2(d[i][j][2], d[i][j][3]);
        }
    }
}

// Sum split-K partials + bias, LayerNorm over 64 cols. One warp per row.
__global__ __launch_bounds__(256) void ln64_k(
    const float* __restrict__ part, const float* __restrict__ bias,
    const float* __restrict__ lg, const float* __restrict__ lb,
    float* __restrict__ out)
{
    int row  = blockIdx.x * 8 + (threadIdx.x >> 5);
    int lane = threadIdx.x & 31;
    int c0 = lane, c1 = lane + 32;
    float v0 = bias[c0], v1 = bias[c1];
#pragma unroll
    for (int s = 0; s < KSPLIT; s++) {
        const float* p = part + ((size_t)s * NR + row) * DL;
        v0 += p[c0];
        v1 += p[c1];
    }
    float sm = v0 + v1;
#pragma unroll
    for (int o = 16; o; o >>= 1) sm += __shfl_xor_sync(0xffffffffu, sm, o);
    float mu = sm * (1.0f / 64.0f);
    float d0 = v0 - mu, d1 = v1 - mu;
    float sv = fmaf(d0, d0, d1 * d1);
#pragma unroll
    for (int o = 16; o; o >>= 1) sv += __shfl_xor_sync(0xffffffffu, sv, o);
    float rs = rsqrtf(sv * (1.0f / 64.0f) + 1e-9f);
    float* op = out + (size_t)row * DL;
    op[c0] = d0 * rs * lg[c0] + lb[c0];
    op[c1] = d1 * rs * lg[c1] + lb[c1];
}

// ---------------------------------------------------------------------------
// In-place LayerNorm over D=1024, one block per row.
// ---------------------------------------------------------------------------
__device__ __forceinline__ float block_sum_256(float v, float* red) {
#pragma unroll
    for (int o = 16; o; o >>= 1) v += __shfl_xor_sync(0xffffffffu, v, o);
    if ((threadIdx.x & 31) == 0) red[threadIdx.x >> 5] = v;
    __syncthreads();
    float t = 0.0f;
#pragma unroll
    for (int i = 0; i < 8; i++) t += red[i];
    __syncthreads();
    return t;
}

__global__ __launch_bounds__(256) void ln1024(
    float* __restrict__ x, const float* __restrict__ lg, const float* __restrict__ lb)
{
    __shared__ float red[8];
    float* p = x + (size_t)blockIdx.x * DD;
    const int tid = threadIdx.x;
    float v[4];
    float s = 0.0f;
#pragma unroll
    for (int i = 0; i < 4; i++) { v[i] = p[tid + i * 256]; s += v[i]; }
    float mu = block_sum_256(s, red) * (1.0f / 1024.0f);
    float s2 = 0.0f;
#pragma unroll
    for (int i = 0; i < 4; i++) {
        float dd = v[i] - mu;
        s2 = fmaf(dd, dd, s2);
    }
    float var = block_sum_256(s2, red) * (1.0f / 1024.0f);
    float rs = rsqrtf(var + 1e-9f);
#pragma unroll
    for (int i = 0; i < 4; i++) {
        int col = tid + i * 256;
        p[col] = (v[i] - mu) * rs * lg[col] + lb[col];
    }
}

// ---------------------------------------------------------------------------
// Per-row squared norms for DL=64 vectors.
// ---------------------------------------------------------------------------
__global__ __launch_bounds__(256) void rowsq(
    const float* __restrict__ X, float* __restrict__ o)
{
    int row = blockIdx.x * 8 + (threadIdx.x >> 5);
    int lane = threadIdx.x & 31;
    const float* p = X + (size_t)row * DL;
    float a = p[lane], b = p[lane + 32];
    float s = fmaf(a, a, b * b);
#pragma unroll
    for (int off = 16; off; off >>= 1) s += __shfl_xor_sync(0xffffffffu, s, off);
    if (lane == 0) o[row] = s;
}

// ---------------------------------------------------------------------------
// RBF kernel-mean tile; polynomial exp (arg in [0, ~0.15]); symmetry-aware.
// ---------------------------------------------------------------------------
__global__ __launch_bounds__(256) void mmd_tile(
    const float* __restrict__ X, const float* __restrict__ Y,
    const float* __restrict__ x2, const float* __restrict__ y2,
    double* __restrict__ acc, int sym)
{
    const int bi = blockIdx.y, bj = blockIdx.x;
    if (sym && bi > bj) return;

    __shared__ float Xs[64][64];
    __shared__ float Ys[64][64];
    const int tid = threadIdx.x;
    const int i0 = bi * 64, j0 = bj * 64;

#pragma unroll
    for (int i = 0; i < 4; i++) {
        int id = tid + 256 * i;
        int r = id >> 4, c = (id & 15) << 2;
        float4 vx = *(const float4*)(X + (size_t)(i0 + r) * DL + c);
        Xs[c + 0][r] = vx.x; Xs[c + 1][r] = vx.y;
        Xs[c + 2][r] = vx.z; Xs[c + 3][r] = vx.w;
        float4 vy = *(const float4*)(Y + (size_t)(j0 + r) * DL + c);
        Ys[c + 0][r] = vy.x; Ys[c + 1][r] = vy.y;
        Ys[c + 2][r] = vy.z; Ys[c + 3][r] = vy.w;
    }
    __syncthreads();

    const int ty = tid >> 4, tx = tid & 15;
    float s[4][4];
#pragma unroll
    for (int i = 0; i < 4; i++)
#pragma unroll
        for (int j = 0; j < 4; j++) s[i][j] = 0.0f;

#pragma unroll
    for (int k = 0; k < 64; k++) {
        float4 a = *(const float4*)&Xs[k][ty * 4];
        float4 b = *(const float4*)&Ys[k][tx * 4];
        float av[4] = {a.x, a.y, a.z, a.w};
        float bv[4] = {b.x, b.y, b.z, b.w};
#pragma unroll
        for (int i = 0; i < 4; i++)
#pragma unroll
            for (int j = 0; j < 4; j++)
                s[i][j] = fmaf(av[i], bv[j], s[i][j]);
    }

    float xi[4], yj[4];
#pragma unroll
    for (int i = 0; i < 4; i++) xi[i] = x2[i0 + ty * 4 + i];
#pragma unroll
    for (int j = 0; j < 4; j++) yj[j] = y2[j0 + tx * 4 + j];

    float lsum = 0.0f;
#pragma unroll
    for (int i = 0; i < 4; i++)
#pragma unroll
        for (int j = 0; j < 4; j++) {
            float sq = xi[i] + yj[j] - 2.0f * s[i][j];
            float t = sq * (1.0f / 4096.0f);
            // exp(-t), degree-6 Taylor: |err| < 2e-6 for t in [0, 0.5]
            float e = fmaf(t, -1.0f / 720.0f, 1.0f / 120.0f);
            e = fmaf(t, e, -1.0f / 24.0f);
            e = fmaf(t, e, 1.0f / 6.0f);
            e = fmaf(t, e, -0.5f);
            e = fmaf(t, e, 1.0f);
            e = fmaf(-t, e, 1.0f);   // 1 - t*(1 - t/2 + ...)
            if (t > 0.5f) e = __expf(-t);
            lsum += e;
        }

    if (sym && bi != bj) lsum *= 2.0f;

#pragma unroll
    for (int off = 16; off; off >>= 1)
        lsum += __shfl_xor_sync(0xffffffffu, lsum, off);

    __shared__ float ws[8];
    if ((tid & 31) == 0) ws[tid >> 5] = lsum;
    __syncthreads();
    if (tid == 0) {
        double t = 0.0;
#pragma unroll
        for (int w = 0; w < 8; w++) t += (double)ws[w];
        atomicAdd(acc, t);
    }
}

__global__ void zero_acc_k() {
    if (threadIdx.x < 3) g_acc[threadIdx.x] = 0.0;
}

__global__ void finalize_loss(float* __restrict__ out) {
    const double inv = 1.0 / (4096.0 * 4096.0);
    double mmd = (g_acc[0] + g_acc[1] - 2.0 * g_acc[2]) * inv;
    out[0] = (float)(mmd * 64.0);
}

// ---------------------------------------------------------------------------
extern "C" void kernel_launch(void* const* d_in, const int* in_sizes, int n_in,
                              void* d_out, int out_size)
{
    const float* hidden = (const float*)d_in[0];
    const float* true_s = (const float*)d_in[1];
    const float* enc_w1 = (const float*)d_in[2];
    const float* enc_b1 = (const float*)d_in[3];
    const float* enc_w2 = (const float*)d_in[4];
    const float* enc_b2 = (const float*)d_in[5];
    const float* enc_g  = (const float*)d_in[6];
    const float* enc_lb = (const float*)d_in[7];
    const float* dec_w1 = (const float*)d_in[8];
    const float* dec_b1 = (const float*)d_in[9];
    const float* dec_w2 = (const float*)d_in[10];
    const float* dec_b2 = (const float*)d_in[11];
    const float* dec_g  = (const float*)d_in[12];
    const float* dec_lb = (const float*)d_in[13];

    float* recon  = (float*)d_out;
    float* latent = recon + (size_t)NR * DD;
    float* loss   = latent + (size_t)NR * DL;

    float*  h;    cudaGetSymbolAddress((void**)&h,    g_h);
    float*  part; cudaGetSymbolAddress((void**)&part, g_part);
    float*  x2;   cudaGetSymbolAddress((void**)&x2,   g_x2);
    float*  y2;   cudaGetSymbolAddress((void**)&y2,   g_y2);
    double* acc;  cudaGetSymbolAddress((void**)&acc,  g_acc);

    zero_acc_k<<<1, 32>>>();

    // encoder: h = gelu(hidden @ enc_w1 + b1)   [4096,4096]
    gemm_tc<true><<<dim3(DI / 128, NR / 128), 256>>>(hidden, enc_w1, enc_b1, h,
                                                     NR, DI, DD);
    // latent = LN64(h @ enc_w2 + b2)  (split-K + fused LN)
    gemm2_tc<<<dim3(KSPLIT, NR / 128), 256>>>(h, enc_w2, part);
    ln64_k<<<NR / 8, 256>>>(part, enc_b2, enc_g, enc_lb, latent);

    // decoder
    gemm_tc<true><<<dim3(DI / 128, NR / 128), 256>>>(latent, dec_w1, dec_b1, h,
                                                     NR, DI, DL);
    gemm_tc<false><<<dim3(DD / 128, NR / 128), 256>>>(h, dec_w2, dec_b2, recon,
                                                      NR, DD, DI);
    ln1024<<<NR, 256>>>(recon, dec_g, dec_lb);

    // MMD
    rowsq<<<NR / 8, 256>>>(true_s, x2);
    rowsq<<<NR / 8, 256>>>(latent, y2);
    mmd_tile<<<dim3(64, 64), 256>>>(true_s, true_s, x2, x2, acc + 0, 1);
    mmd_tile<<<dim3(64, 64), 256>>>(latent, latent, y2, y2, acc + 1, 1);
    mmd_tile<<<dim3(64, 64), 256>>>(true_s, latent, x2, y2, acc + 2, 0);
    finalize_loss<<<1, 1>>>(loss);
}

// round 4
// speedup vs baseline: 2.9543x; 1.0958x over previous
#include <cuda_runtime.h>
#include <math.h>

#define NR 4096
#define DD 1024
#define DI 4096
#define DL 64
#define KSPLIT 8

// scratch
__device__ float g_h[(size_t)4096 * 4096];           // 64MB hidden activations
__device__ float g_part[(size_t)KSPLIT * 4096 * 64]; // 8MB split-K partials
__device__ float g_x2[4096];
__device__ float g_y2[4096];
__device__ double g_acc[3];

__device__ __forceinline__ float gelu_f(float x) {
    return 0.5f * x * (1.0f + erff(x * 0.70710678118654752440f));
}

__device__ __forceinline__ unsigned f2tf32(float x) {
    unsigned u;
    asm("cvt.rna.tf32.f32 %0, %1;" : "=r"(u) : "f"(x));
    return u;
}

__device__ __forceinline__ void mma_tf32(float* d, const unsigned* a, const unsigned* b) {
    asm volatile(
        "mma.sync.aligned.m16n8k8.row.col.f32.tf32.tf32.f32 "
        "{%0,%1,%2,%3}, {%4,%5,%6,%7}, {%8,%9}, {%0,%1,%2,%3};\n"
        : "+f"(d[0]), "+f"(d[1]), "+f"(d[2]), "+f"(d[3])
        : "r"(a[0]), "r"(a[1]), "r"(a[2]), "r"(a[3]), "r"(b[0]), "r"(b[1]));
}

__device__ __forceinline__ void cp16(float* dst_smem, const float* src) {
    unsigned d = (unsigned)__cvta_generic_to_shared(dst_smem);
    asm volatile("cp.async.cg.shared.global [%0], [%1], 16;\n" :: "r"(d), "l"(src));
}

// smem layout constants for the pipelined GEMM
#define AS_STRIDE 36
#define BS_STRIDE 136
#define AS_ELEMS (128 * AS_STRIDE)   // per stage
#define BS_ELEMS (32 * BS_STRIDE)    // per stage
#define NSTAGES 3
#define GEMM_SMEM_BYTES (NSTAGES * (AS_ELEMS + BS_ELEMS) * 4)

// ---------------------------------------------------------------------------
// TF32 tensor-core GEMM, 3-stage cp.async pipeline:
//   C[M,N] = A[M,K] @ B[K,N] + bias, optional exact GELU.
// BM=128 BN=128 BK=32, 256 threads (8 warps, 2m x 4n), warp tile 64x32.
// fp32 lives in smem; cvt.rna.tf32 at fragment load (numerics == previous rev).
// ---------------------------------------------------------------------------
template <bool GELU>
__global__ __launch_bounds__(256, 2) void gemm_tc(
    const float* __restrict__ A, const float* __restrict__ B,
    const float* __restrict__ bias, float* __restrict__ C,
    int M, int N, int K)
{
    extern __shared__ float smem[];
    float* Asm = smem;                        // NSTAGES * AS_ELEMS
    float* Bsm = smem + NSTAGES * AS_ELEMS;   // NSTAGES * BS_ELEMS

    const int tid  = threadIdx.x;
    const int warp = tid >> 5, lane = tid & 31;
    const int gid  = lane >> 2, tig = lane & 3;
    const int wm   = (warp & 1) * 64;
    const int wn   = (warp >> 1) * 32;
    const int bm   = blockIdx.y * 128;
    const int bn   = blockIdx.x * 128;

    // per-thread load coords (fixed across tiles)
    const int ar = tid >> 1, ac = (tid & 1) << 4;         // A: 128 rows x 32 cols, 2 f4/row -> 4 f4/thread via it
    const int br = tid >> 5, bc = (tid & 31) << 2;        // B: 32 rows x 128 cols

    auto load_stage = [&](int k0, int s) {
        float* a = Asm + s * AS_ELEMS;
        float* b = Bsm + s * BS_ELEMS;
#pragma unroll
        for (int it = 0; it < 4; it++) {
            int id = tid + 256 * it;
            int r = id >> 3, c = (id & 7) << 2;
            cp16(a + r * AS_STRIDE + c, A + (size_t)(bm + r) * K + k0 + c);
        }
#pragma unroll
        for (int it = 0; it < 4; it++) {
            int id = tid + 256 * it;
            int r = id >> 5, c = (id & 31) << 2;
            cp16(b + r * BS_STRIDE + c, B + (size_t)(k0 + r) * N + bn + c);
        }
        asm volatile("cp.async.commit_group;\n");
    };
    (void)ar; (void)ac; (void)br; (void)bc;

    float d[4][4][4];
#pragma unroll
    for (int i = 0; i < 4; i++)
#pragma unroll
        for (int j = 0; j < 4; j++)
#pragma unroll
            for (int r = 0; r < 4; r++) d[i][j][r] = 0.0f;

    const int T = K >> 5;   // number of 32-wide K tiles (K multiple of 32, >= 64)
    load_stage(0, 0);
    if (T > 1) load_stage(32, 1);

    for (int i = 0; i < T; i++) {
        if (i + 1 < T) {
            asm volatile("cp.async.wait_group 1;\n");
        } else {
            asm volatile("cp.async.wait_group 0;\n");
        }
        __syncthreads();

        const float* a = Asm + (i % NSTAGES) * AS_ELEMS;
        const float* b = Bsm + (i % NSTAGES) * BS_ELEMS;

#pragma unroll
        for (int ks = 0; ks < 4; ks++) {
            const int k8 = ks * 8;
            unsigned af[4][4], bf[4][2];
#pragma unroll
            for (int ii = 0; ii < 4; ii++) {
                int m = wm + 16 * ii + gid;
                af[ii][0] = f2tf32(a[m * AS_STRIDE + k8 + tig]);
                af[ii][1] = f2tf32(a[(m + 8) * AS_STRIDE + k8 + tig]);
                af[ii][2] = f2tf32(a[m * AS_STRIDE + k8 + tig + 4]);
                af[ii][3] = f2tf32(a[(m + 8) * AS_STRIDE + k8 + tig + 4]);
            }
#pragma unroll
            for (int j = 0; j < 4; j++) {
                int n = wn + 8 * j + gid;
                bf[j][0] = f2tf32(b[(k8 + tig) * BS_STRIDE + n]);
                bf[j][1] = f2tf32(b[(k8 + tig + 4) * BS_STRIDE + n]);
            }
#pragma unroll
            for (int ii = 0; ii < 4; ii++)
#pragma unroll
                for (int j = 0; j < 4; j++)
                    mma_tf32(d[ii][j], af[ii], bf[j]);
        }

        if (i + 2 < T) load_stage((i + 2) * 32, (i + 2) % NSTAGES);
    }

#pragma unroll
    for (int i = 0; i < 4; i++) {
        int row = bm + wm + 16 * i + gid;
#pragma unroll
        for (int j = 0; j < 4; j++) {
            int col = bn + wn + 8 * j + 2 * tig;
            float bx = bias[col], by = bias[col + 1];
            float r0 = d[i][j][0] + bx, r1 = d[i][j][1] + by;
            float r2 = d[i][j][2] + bx, r3 = d[i][j][3] + by;
            if (GELU) {
                r0 = gelu_f(r0); r1 = gelu_f(r1);
                r2 = gelu_f(r2); r3 = gelu_f(r3);
            }
            *(float2*)(C + (size_t)row * N + col)       = make_float2(r0, r1);
            *(float2*)(C + (size_t)(row + 8) * N + col) = make_float2(r2, r3);
        }
    }
}

// ---------------------------------------------------------------------------
// GEMM2 split-K (tf32): part[ks][4096,64] = A[:,ks*512:+512] @ B-slice
// BM=128 BN=64 BK=32, 8 warps (4m x 2n), warp tile 32x32.
// ---------------------------------------------------------------------------
__global__ __launch_bounds__(256, 2) void gemm2_tc(
    const float* __restrict__ A, const float* __restrict__ B,
    float* __restrict__ part)
{
    __shared__ float As[128][36];
    __shared__ float Bs[32][72];

    const int tid  = threadIdx.x;
    const int warp = tid >> 5, lane = tid & 31;
    const int gid  = lane >> 2, tig = lane & 3;
    const int wm   = (warp & 3) * 32;
    const int wn   = (warp >> 2) * 32;
    const int bm   = blockIdx.y * 128;
    const int kbeg = blockIdx.x * (DI / KSPLIT);

    float d[2][4][4];
#pragma unroll
    for (int i = 0; i < 2; i++)
#pragma unroll
        for (int j = 0; j < 4; j++)
#pragma unroll
            for (int r = 0; r < 4; r++) d[i][j][r] = 0.0f;

    for (int kk = 0; kk < DI / KSPLIT; kk += 32) {
        const int k0 = kbeg + kk;
#pragma unroll
        for (int it = 0; it < 4; it++) {
            int id = tid + 256 * it;
            int r = id >> 3, c = (id & 7) << 2;
            float4 v = *(const float4*)(A + (size_t)(bm + r) * DI + k0 + c);
            float4 w;
            w.x = __uint_as_float(f2tf32(v.x));
            w.y = __uint_as_float(f2tf32(v.y));
            w.z = __uint_as_float(f2tf32(v.z));
            w.w = __uint_as_float(f2tf32(v.w));
            *(float4*)&As[r][c] = w;
        }
#pragma unroll
        for (int it = 0; it < 2; it++) {
            int id = tid + 256 * it;
            int r = id >> 4, c = (id & 15) << 2;
            float4 v = *(const float4*)(B + (size_t)(k0 + r) * DL + c);
            float4 w;
            w.x = __uint_as_float(f2tf32(v.x));
            w.y = __uint_as_float(f2tf32(v.y));
            w.z = __uint_as_float(f2tf32(v.z));
            w.w = __uint_as_float(f2tf32(v.w));
            *(float4*)&Bs[r][c] = w;
        }
        __syncthreads();

#pragma unroll
        for (int ks = 0; ks < 4; ks++) {
            const int k8 = ks * 8;
            unsigned a[2][4], bf[4][2];
#pragma unroll
            for (int i = 0; i < 2; i++) {
                int m = wm + 16 * i + gid;
                a[i][0] = __float_as_uint(As[m][k8 + tig]);
                a[i][1] = __float_as_uint(As[m + 8][k8 + tig]);
                a[i][2] = __float_as_uint(As[m][k8 + tig + 4]);
                a[i][3] = __float_as_uint(As[m + 8][k8 + tig + 4]);
            }
#pragma unroll
            for (int j = 0; j < 4; j++) {
                int n = wn + 8 * j + gid;
                bf[j][0] = __float_as_uint(Bs[k8 + tig][n]);
                bf[j][1] = __float_as_uint(Bs[k8 + tig + 4][n]);
            }
#pragma unroll
            for (int i = 0; i < 2; i++)
#pragma unroll
                for (int j = 0; j < 4; j++)
                    mma_tf32(d[i][j], a[i], bf[j]);
        }
        __syncthreads();
    }

    float* op = part + (size_t)blockIdx.x * NR * DL;
#pragma unroll
    for (int i = 0; i < 2; i++) {
        int row = bm + wm + 16 * i + gid;
#pragma unroll
        for (int j = 0; j < 4; j++) {
            int col = wn + 8 * j + 2 * tig;
            *(float2*)(op + (size_t)row * DL + col)       = make_float2(d[i][j][0], d[i][j][1]);
            *(float2*)(op + (size_t)(row + 8) * DL + col) = make_float2(d[i][j][2], d[i][j][3]);
        }
    }
}

// Sum split-K partials + bias, LayerNorm over 64 cols. One warp per row.
__global__ __launch_bounds__(256) void ln64_k(
    const float* __restrict__ part, const float* __restrict__ bias,
    const float* __restrict__ lg, const float* __restrict__ lb,
    float* __restrict__ out)
{
    int row  = blockIdx.x * 8 + (threadIdx.x >> 5);
    int lane = threadIdx.x & 31;
    int c0 = lane, c1 = lane + 32;
    float v0 = bias[c0], v1 = bias[c1];
#pragma unroll
    for (int s = 0; s < KSPLIT; s++) {
        const float* p = part + ((size_t)s * NR + row) * DL;
        v0 += p[c0];
        v1 += p[c1];
    }
    float sm = v0 + v1;
#pragma unroll
    for (int o = 16; o; o >>= 1) sm += __shfl_xor_sync(0xffffffffu, sm, o);
    float mu = sm * (1.0f / 64.0f);
    float d0 = v0 - mu, d1 = v1 - mu;
    float sv = fmaf(d0, d0, d1 * d1);
#pragma unroll
    for (int o = 16; o; o >>= 1) sv += __shfl_xor_sync(0xffffffffu, sv, o);
    float rs = rsqrtf(sv * (1.0f / 64.0f) + 1e-9f);
    float* op = out + (size_t)row * DL;
    op[c0] = d0 * rs * lg[c0] + lb[c0];
    op[c1] = d1 * rs * lg[c1] + lb[c1];
}

// ---------------------------------------------------------------------------
// In-place LayerNorm over D=1024, one block per row.
// ---------------------------------------------------------------------------
__device__ __forceinline__ float block_sum_256(float v, float* red) {
#pragma unroll
    for (int o = 16; o; o >>= 1) v += __shfl_xor_sync(0xffffffffu, v, o);
    if ((threadIdx.x & 31) == 0) red[threadIdx.x >> 5] = v;
    __syncthreads();
    float t = 0.0f;
#pragma unroll
    for (int i = 0; i < 8; i++) t += red[i];
    __syncthreads();
    return t;
}

__global__ __launch_bounds__(256) void ln1024(
    float* __restrict__ x, const float* __restrict__ lg, const float* __restrict__ lb)
{
    __shared__ float red[8];
    float* p = x + (size_t)blockIdx.x * DD;
    const int tid = threadIdx.x;
    float v[4];
    float s = 0.0f;
#pragma unroll
    for (int i = 0; i < 4; i++) { v[i] = p[tid + i * 256]; s += v[i]; }
    float mu = block_sum_256(s, red) * (1.0f / 1024.0f);
    float s2 = 0.0f;
#pragma unroll
    for (int i = 0; i < 4; i++) {
        float dd = v[i] - mu;
        s2 = fmaf(dd, dd, s2);
    }
    float var = block_sum_256(s2, red) * (1.0f / 1024.0f);
    float rs = rsqrtf(var + 1e-9f);
#pragma unroll
    for (int i = 0; i < 4; i++) {
        int col = tid + i * 256;
        p[col] = (v[i] - mu) * rs * lg[col] + lb[col];
    }
}

// ---------------------------------------------------------------------------
// Per-row squared norms for DL=64 vectors.
// ---------------------------------------------------------------------------
__global__ __launch_bounds__(256) void rowsq(
    const float* __restrict__ X, float* __restrict__ o)
{
    int row = blockIdx.x * 8 + (threadIdx.x >> 5);
    int lane = threadIdx.x & 31;
    const float* p = X + (size_t)row * DL;
    float a = p[lane], b = p[lane + 32];
    float s = fmaf(a, a, b * b);
#pragma unroll
    for (int off = 16; off; off >>= 1) s += __shfl_xor_sync(0xffffffffu, s, off);
    if (lane == 0) o[row] = s;
}

// ---------------------------------------------------------------------------
// RBF kernel-mean tile; polynomial exp (arg in [0, ~0.15]); symmetry-aware.
// fp32 dots on purpose: loss scalar sits on a Kxx+Kyy-2Kxy cancellation.
// ---------------------------------------------------------------------------
__global__ __launch_bounds__(256) void mmd_tile(
    const float* __restrict__ X, const float* __restrict__ Y,
    const float* __restrict__ x2, const float* __restrict__ y2,
    double* __restrict__ acc, int sym)
{
    const int bi = blockIdx.y, bj = blockIdx.x;
    if (sym && bi > bj) return;

    __shared__ float Xs[64][64];
    __shared__ float Ys[64][64];
    const int tid = threadIdx.x;
    const int i0 = bi * 64, j0 = bj * 64;

#pragma unroll
    for (int i = 0; i < 4; i++) {
        int id = tid + 256 * i;
        int r = id >> 4, c = (id & 15) << 2;
        float4 vx = *(const float4*)(X + (size_t)(i0 + r) * DL + c);
        Xs[c + 0][r] = vx.x; Xs[c + 1][r] = vx.y;
        Xs[c + 2][r] = vx.z; Xs[c + 3][r] = vx.w;
        float4 vy = *(const float4*)(Y + (size_t)(j0 + r) * DL + c);
        Ys[c + 0][r] = vy.x; Ys[c + 1][r] = vy.y;
        Ys[c + 2][r] = vy.z; Ys[c + 3][r] = vy.w;
    }
    __syncthreads();

    const int ty = tid >> 4, tx = tid & 15;
    float s[4][4];
#pragma unroll
    for (int i = 0; i < 4; i++)
#pragma unroll
        for (int j = 0; j < 4; j++) s[i][j] = 0.0f;

#pragma unroll
    for (int k = 0; k < 64; k++) {
        float4 a = *(const float4*)&Xs[k][ty * 4];
        float4 b = *(const float4*)&Ys[k][tx * 4];
        float av[4] = {a.x, a.y, a.z, a.w};
        float bv[4] = {b.x, b.y, b.z, b.w};
#pragma unroll
        for (int i = 0; i < 4; i++)
#pragma unroll
            for (int j = 0; j < 4; j++)
                s[i][j] = fmaf(av[i], bv[j], s[i][j]);
    }

    float xi[4], yj[4];
#pragma unroll
    for (int i = 0; i < 4; i++) xi[i] = x2[i0 + ty * 4 + i];
#pragma unroll
    for (int j = 0; j < 4; j++) yj[j] = y2[j0 + tx * 4 + j];

    float lsum = 0.0f;
#pragma unroll
    for (int i = 0; i < 4; i++)
#pragma unroll
        for (int j = 0; j < 4; j++) {
            float sq = xi[i] + yj[j] - 2.0f * s[i][j];
            float t = sq * (1.0f / 4096.0f);
            float e = fmaf(t, -1.0f / 720.0f, 1.0f / 120.0f);
            e = fmaf(t, e, -1.0f / 24.0f);
            e = fmaf(t, e, 1.0f / 6.0f);
            e = fmaf(t, e, -0.5f);
            e = fmaf(t, e, 1.0f);
            e = fmaf(-t, e, 1.0f);
            if (t > 0.5f) e = __expf(-t);
            lsum += e;
        }

    if (sym && bi != bj) lsum *= 2.0f;

#pragma unroll
    for (int off = 16; off; off >>= 1)
        lsum += __shfl_xor_sync(0xffffffffu, lsum, off);

    __shared__ float ws[8];
    if ((tid & 31) == 0) ws[tid >> 5] = lsum;
    __syncthreads();
    if (tid == 0) {
        double t = 0.0;
#pragma unroll
        for (int w = 0; w < 8; w++) t += (double)ws[w];
        atomicAdd(acc, t);
    }
}

__global__ void zero_acc_k() {
    if (threadIdx.x < 3) g_acc[threadIdx.x] = 0.0;
}

__global__ void finalize_loss(float* __restrict__ out) {
    const double inv = 1.0 / (4096.0 * 4096.0);
    double mmd = (g_acc[0] + g_acc[1] - 2.0 * g_acc[2]) * inv;
    out[0] = (float)(mmd * 64.0);
}

// ---------------------------------------------------------------------------
extern "C" void kernel_launch(void* const* d_in, const int* in_sizes, int n_in,
                              void* d_out, int out_size)
{
    const float* hidden = (const float*)d_in[0];
    const float* true_s = (const float*)d_in[1];
    const float* enc_w1 = (const float*)d_in[2];
    const float* enc_b1 = (const float*)d_in[3];
    const float* enc_w2 = (const float*)d_in[4];
    const float* enc_b2 = (const float*)d_in[5];
    const float* enc_g  = (const float*)d_in[6];
    const float* enc_lb = (const float*)d_in[7];
    const float* dec_w1 = (const float*)d_in[8];
    const float* dec_b1 = (const float*)d_in[9];
    const float* dec_w2 = (const float*)d_in[10];
    const float* dec_b2 = (const float*)d_in[11];
    const float* dec_g  = (const float*)d_in[12];
    const float* dec_lb = (const float*)d_in[13];

    float* recon  = (float*)d_out;
    float* latent = recon + (size_t)NR * DD;
    float* loss   = latent + (size_t)NR * DL;

    float*  h;    cudaGetSymbolAddress((void**)&h,    g_h);
    float*  part; cudaGetSymbolAddress((void**)&part, g_part);
    float*  x2;   cudaGetSymbolAddress((void**)&x2,   g_x2);
    float*  y2;   cudaGetSymbolAddress((void**)&y2,   g_y2);
    double* acc;  cudaGetSymbolAddress((void**)&acc,  g_acc);

    static int smem_set = 0;
    if (!smem_set) {
        cudaFuncSetAttribute(gemm_tc<true>,
                             cudaFuncAttributeMaxDynamicSharedMemorySize,
                             GEMM_SMEM_BYTES);
        cudaFuncSetAttribute(gemm_tc<false>,
                             cudaFuncAttributeMaxDynamicSharedMemorySize,
                             GEMM_SMEM_BYTES);
        smem_set = 1;
    }

    zero_acc_k<<<1, 32>>>();

    // encoder: h = gelu(hidden @ enc_w1 + b1)   [4096,4096]
    gemm_tc<true><<<dim3(DI / 128, NR / 128), 256, GEMM_SMEM_BYTES>>>(
        hidden, enc_w1, enc_b1, h, NR, DI, DD);
    // latent = LN64(h @ enc_w2 + b2)  (split-K + fused LN)
    gemm2_tc<<<dim3(KSPLIT, NR / 128), 256>>>(h, enc_w2, part);
    ln64_k<<<NR / 8, 256>>>(part, enc_b2, enc_g, enc_lb, latent);

    // decoder
    gemm_tc<true><<<dim3(DI / 128, NR / 128), 256, GEMM_SMEM_BYTES>>>(
        latent, dec_w1, dec_b1, h, NR, DI, DL);
    gemm_tc<false><<<dim3(DD / 128, NR / 128), 256, GEMM_SMEM_BYTES>>>(
        h, dec_w2, dec_b2, recon, NR, DD, DI);
    ln1024<<<NR, 256>>>(recon, dec_g, dec_lb);

    // MMD
    rowsq<<<NR / 8, 256>>>(true_s, x2);
    rowsq<<<NR / 8, 256>>>(latent, y2);
    mmd_tile<<<dim3(64, 64), 256>>>(true_s, true_s, x2, x2, acc + 0, 1);
    mmd_tile<<<dim3(64, 64), 256>>>(latent, latent, y2, y2, acc + 1, 1);
    mmd_tile<<<dim3(64, 64), 256>>>(true_s, latent, x2, y2, acc + 2, 0);
    finalize_loss<<<1, 1>>>(loss);
}